// round 14
// baseline (speedup 1.0000x reference)
#include <cuda_runtime.h>
#include <cuda_bf16.h>

#define D        1024
#define NBLK     6
#define NV       7            // 6 blocks + partial
#define THREADS  512
#define NWARP    16
#define REPS     1e-6f
#define INV_SCALE (1.0f/32.0f)   // 1/(sqrt(1024)*temperature)
#define GRID     296             // 2 CTAs/SM x 148 SMs, one exact wave

__global__ __launch_bounds__(THREADS, 2)
void reskip_kernel(const float* __restrict__ blocks,
                   const float* __restrict__ partial,
                   const float* __restrict__ w_query,
                   const float* __restrict__ norm_w,
                   float* __restrict__ out,
                   int bt, long long blk_stride)
{
    __shared__ float s_red[2][NWARP * 16];      // double-buffered [warp][value]

    const int tid  = threadIdx.x;
    const int warp = tid >> 5, lane = tid & 31;
    const int j    = tid * 2;                   // this thread's 2 channels
    const int stride = gridDim.x;
    const long long dstep = (long long)stride * D;   // token-stride in floats

    // effective query = w_query * norm_weight (fp32)
    float2 q2  = *(const float2*)(w_query + j);
    float2 nw2 = *(const float2*)(norm_w  + j);
    const float q0 = q2.x * nw2.x, q1 = q2.y * nw2.y;

    int tok = blockIdx.x;
    if (tok >= bt) return;

    long long base = (long long)tok * D + j;

    // ---- prologue: load first token into cur registers
    float cx0[NV], cx1[NV];
    {
        #pragma unroll
        for (int n = 0; n < NBLK; n++) {
            float2 d = *(const float2*)(blocks + (long long)n * blk_stride + base);
            cx0[n] = d.x; cx1[n] = d.y;
        }
        float2 d = *(const float2*)(partial + base);
        cx0[6] = d.x; cx1[6] = d.y;
    }

    int p = 0;
    while (tok < bt) {
        const int ntok = tok + stride;

        // ---- score partials from cur data
        //   v[0..6] = q.x per vector, v[7..13] = x.x, v[14..15] = pad
        float v[16];
        #pragma unroll
        for (int n = 0; n < NV; n++) {
            v[n]     = fmaf(q1, cx1[n], q0 * cx0[n]);
            v[n + 7] = fmaf(cx1[n], cx1[n], cx0[n] * cx0[n]);
        }
        v[14] = 0.f; v[15] = 0.f;

        // ---- prefetch next token NOW; DRAM latency hides under the
        // butterfly/barrier/epilogue below. Tail-safe: re-load cur token.
        const long long nbase = base + ((ntok < bt) ? dstep : 0);
        float nx0[NV], nx1[NV];
        {
            #pragma unroll
            for (int n = 0; n < NBLK; n++) {
                float2 d = *(const float2*)(blocks + (long long)n * blk_stride + nbase);
                nx0[n] = d.x; nx1[n] = d.y;
            }
            float2 d = *(const float2*)(partial + nbase);
            nx0[6] = d.x; nx1[6] = d.y;
        }

        // ---- value-specializing butterfly: 16 values, 16 SHFL total.
        // Final: lane l holds the full-warp sum of value (l >> 1).
        #pragma unroll
        for (int off = 16, k = 8; off >= 2; off >>= 1, k >>= 1) {
            #pragma unroll
            for (int i = 0; i < 8; i++) {
                if (i < k) {
                    float send = (lane & off) ? v[i] : v[i + k];
                    float recv = __shfl_xor_sync(0xffffffffu, send, off);
                    v[i] = ((lane & off) ? v[i + k] : v[i]) + recv;
                }
            }
        }
        v[0] += __shfl_xor_sync(0xffffffffu, v[0], 1);

        if (!(lane & 1) && (lane >> 1) < 14)
            s_red[p][warp * 16 + (lane >> 1)] = v[0];
        __syncthreads();        // the ONLY barrier per iteration

        // ---- decentralized scalar phase: EVERY warp computes the 7
        // coefficients in registers (cheap: __expf = MUFU, warp-wide).
        float t = 0.f;
        if (lane < 14) {
            #pragma unroll
            for (int w = 0; w < NWARP; w++) t += s_red[p][w * 16 + lane];
        }
        float xxv = __shfl_sync(0xffffffffu, t, (lane + 7) & 31);
        float mysc = 0.f;
        if (lane < NV) {
            float inv = rsqrtf(xxv * (1.0f / (float)D) + REPS);
            mysc = t * inv * INV_SCALE;
        }
        float sc[NV];
        #pragma unroll
        for (int n = 0; n < NV; n++) sc[n] = __shfl_sync(0xffffffffu, mysc, n);

        // Phase-1 softmax over the 6 completed blocks (all lanes, redundant)
        float m1 = sc[0];
        #pragma unroll
        for (int n = 1; n < NBLK; n++) m1 = fmaxf(m1, sc[n]);
        float es[NBLK], lse = 0.f;
        #pragma unroll
        for (int n = 0; n < NBLK; n++) { es[n] = __expf(sc[n] - m1); lse += es[n]; }

        // Online-softmax merge with partial block
        float ps    = sc[6];
        float mm    = fmaxf(m1, ps);
        float c1    = __expf(m1 - mm);
        float cp    = __expf(ps - mm);
        float denom = c1 * lse + cp;
        float w1w   = c1 * lse / denom;     // phase1_weight
        float pw    = cp / denom;           // partial_weight

        float cc[NV];
        #pragma unroll
        for (int n = 0; n < NBLK; n++) cc[n] = w1w * es[n];
        cc[6] = pw;

        if (tid == 0) {
            float logl = __logf(lse);
            float ent1 = 0.f;
            #pragma unroll
            for (int n = 0; n < NBLK; n++)
                ent1 -= (es[n] / lse) * ((sc[n] - m1) - logl);
            float w1c = fmaxf(w1w, 1e-8f);
            float wpc = fmaxf(pw,  1e-8f);
            out[(long long)bt * D + tok] =
                w1c * ent1 - w1c * __logf(w1c) - wpc * __logf(wpc);
        }

        // ---- epilogue: coefficients and data both in registers
        float o0 = 0.f, o1 = 0.f;
        #pragma unroll
        for (int n = 0; n < NV; n++) {
            o0 = fmaf(cc[n], cx0[n], o0);
            o1 = fmaf(cc[n], cx1[n], o1);
        }
        *(float2*)(out + base) = make_float2(o0, o1);

        // ---- rotate pipeline (s_red double-buffer makes this WAR-safe
        // without a second barrier)
        #pragma unroll
        for (int n = 0; n < NV; n++) { cx0[n] = nx0[n]; cx1[n] = nx1[n]; }
        base = nbase;
        tok  = ntok;
        p   ^= 1;
    }
}

extern "C" void kernel_launch(void* const* d_in, const int* in_sizes, int n_in,
                              void* d_out, int out_size)
{
    const float* blocks  = (const float*)d_in[0];   // [6, b, t, d]
    const float* partial = (const float*)d_in[1];   // [b, t, d]
    const float* wq      = (const float*)d_in[2];   // [d]
    const float* nw      = (const float*)d_in[3];   // [d]
    float* out           = (float*)d_out;           // [b*t*d hidden][b*t entropy]

    int bt = in_sizes[1] / D;                       // b*t tokens
    long long blk_stride = (long long)in_sizes[0] / NBLK;  // b*t*d

    int grid = GRID < bt ? GRID : bt;
    reskip_kernel<<<grid, THREADS>>>(blocks, partial, wq, nw, out, bt, blk_stride);
}

// round 16
// speedup vs baseline: 1.1460x; 1.1460x over previous
#include <cuda_runtime.h>
#include <cuda_bf16.h>

#define D        1024
#define NBLK     6
#define NV       7            // 6 blocks + partial
#define THREADS  256
#define NWARP    8
#define REPS     1e-6f
#define INV_SCALE (1.0f/32.0f)   // 1/(sqrt(1024)*temperature)
#define GRID     444             // 3 CTAs/SM x 148 SMs, one exact wave

__global__ __launch_bounds__(THREADS, 3)
void reskip_kernel(const float* __restrict__ blocks,
                   const float* __restrict__ partial,
                   const float* __restrict__ w_query,
                   const float* __restrict__ norm_w,
                   float* __restrict__ out,
                   int bt, long long blk_stride)
{
    __shared__ float s_red[NWARP * 16];         // [warp][value]
    __shared__ float s_sc[NV];                  // per-vector scores
    __shared__ __align__(16) float s_coef[8];   // c[0..5]=w1*es[n], c[6]=pw, c[7]=0

    const int tid  = threadIdx.x;
    const int warp = tid >> 5, lane = tid & 31;
    const int j    = tid * 4;                   // this thread's 4 channels
    const int stride = gridDim.x;
    const long long dstep = (long long)stride * D;   // token-stride in floats

    // effective query = w_query * norm_weight (fp32)
    float4 q4  = *(const float4*)(w_query + j);
    float4 nw4 = *(const float4*)(norm_w  + j);
    const float q0 = q4.x*nw4.x, q1 = q4.y*nw4.y, q2 = q4.z*nw4.z, q3 = q4.w*nw4.w;

    int tok = blockIdx.x;
    if (tok >= bt) return;

    long long base = (long long)tok * D + j;

    // ---- prologue: load first token into cur registers (7 x float4)
    float4 cx[NV];
    {
        #pragma unroll
        for (int n = 0; n < NBLK; n++)
            cx[n] = *(const float4*)(blocks + (long long)n * blk_stride + base);
        cx[6] = *(const float4*)(partial + base);
    }

    while (tok < bt) {
        const int ntok = tok + stride;

        // ---- prefetch next token FIRST; its DRAM latency hides under the
        // partials/butterfly/barriers/epilogue below. Tail-safe: re-load cur.
        const long long nbase = base + ((ntok < bt) ? dstep : 0);
        float4 nx[NV];
        {
            #pragma unroll
            for (int n = 0; n < NBLK; n++)
                nx[n] = *(const float4*)(blocks + (long long)n * blk_stride + nbase);
            nx[6] = *(const float4*)(partial + nbase);
        }

        // ---- score partials from cur data
        //   v[0..6] = q.x per vector, v[7..13] = x.x, v[14..15] = pad
        float v[16];
        #pragma unroll
        for (int n = 0; n < NV; n++) {
            float a, s;
            a = q0 * cx[n].x;          s = cx[n].x * cx[n].x;
            a = fmaf(q1, cx[n].y, a);  s = fmaf(cx[n].y, cx[n].y, s);
            a = fmaf(q2, cx[n].z, a);  s = fmaf(cx[n].z, cx[n].z, s);
            a = fmaf(q3, cx[n].w, a);  s = fmaf(cx[n].w, cx[n].w, s);
            v[n] = a; v[n + 7] = s;
        }
        v[14] = 0.f; v[15] = 0.f;

        // ---- value-specializing butterfly: 16 values, 16 SHFL total.
        // Final: lane l holds the full-warp sum of value (l >> 1).
        #pragma unroll
        for (int off = 16, k = 8; off >= 2; off >>= 1, k >>= 1) {
            #pragma unroll
            for (int i = 0; i < 8; i++) {
                if (i < k) {
                    float send = (lane & off) ? v[i] : v[i + k];
                    float recv = __shfl_xor_sync(0xffffffffu, send, off);
                    v[i] = ((lane & off) ? v[i + k] : v[i]) + recv;
                }
            }
        }
        v[0] += __shfl_xor_sync(0xffffffffu, v[0], 1);

        if (!(lane & 1) && (lane >> 1) < 14)
            s_red[warp * 16 + (lane >> 1)] = v[0];
        __syncthreads();

        if (warp == 0) {
            float t = 0.f;
            if (lane < 14) {
                #pragma unroll
                for (int w = 0; w < NWARP; w++) t += s_red[w * 16 + lane];
            }
            float xxv = __shfl_sync(0xffffffffu, t, (lane + 7) & 31);
            if (lane < NV) {
                float inv = rsqrtf(xxv * (1.0f / (float)D) + REPS);
                s_sc[lane] = t * inv * INV_SCALE;
            }
            __syncwarp();

            if (lane == 0) {
                float sc[NV];
                #pragma unroll
                for (int n = 0; n < NV; n++) sc[n] = s_sc[n];

                // Phase-1 softmax (fast MUFU transcendentals)
                float m1 = sc[0];
                #pragma unroll
                for (int n = 1; n < NBLK; n++) m1 = fmaxf(m1, sc[n]);
                float es[NBLK], lse = 0.f;
                #pragma unroll
                for (int n = 0; n < NBLK; n++) { es[n] = __expf(sc[n] - m1); lse += es[n]; }
                float logl = __logf(lse);
                float ent1 = 0.f;
                #pragma unroll
                for (int n = 0; n < NBLK; n++)
                    ent1 -= (es[n] / lse) * ((sc[n] - m1) - logl);

                // Online-softmax merge with partial block
                float ps    = sc[6];
                float mm    = fmaxf(m1, ps);
                float c1    = __expf(m1 - mm);
                float cp    = __expf(ps - mm);
                float denom = c1 * lse + cp;
                float w1w   = c1 * lse / denom;     // phase1_weight
                float pw    = cp / denom;           // partial_weight

                #pragma unroll
                for (int n = 0; n < NBLK; n++) s_coef[n] = w1w * es[n];
                s_coef[6] = pw;
                s_coef[7] = 0.f;

                float w1c = fmaxf(w1w, 1e-8f);
                float wpc = fmaxf(pw,  1e-8f);
                out[(long long)bt * D + tok] =
                    w1c * ent1 - w1c * __logf(w1c) - wpc * __logf(wpc);
            }
        }
        __syncthreads();

        // ---- epilogue: coefficients via 2 vector LDS, data from registers
        float4 cA = *(const float4*)&s_coef[0];
        float4 cB = *(const float4*)&s_coef[4];
        const float cc[NV] = { cA.x, cA.y, cA.z, cA.w, cB.x, cB.y, cB.z };

        float o0 = 0.f, o1 = 0.f, o2 = 0.f, o3 = 0.f;
        #pragma unroll
        for (int n = 0; n < NV; n++) {
            o0 = fmaf(cc[n], cx[n].x, o0);
            o1 = fmaf(cc[n], cx[n].y, o1);
            o2 = fmaf(cc[n], cx[n].z, o2);
            o3 = fmaf(cc[n], cx[n].w, o3);
        }
        *(float4*)(out + base) = make_float4(o0, o1, o2, o3);

        // ---- rotate pipeline
        #pragma unroll
        for (int n = 0; n < NV; n++) cx[n] = nx[n];
        base = nbase;
        tok  = ntok;
    }
}

extern "C" void kernel_launch(void* const* d_in, const int* in_sizes, int n_in,
                              void* d_out, int out_size)
{
    const float* blocks  = (const float*)d_in[0];   // [6, b, t, d]
    const float* partial = (const float*)d_in[1];   // [b, t, d]
    const float* wq      = (const float*)d_in[2];   // [d]
    const float* nw      = (const float*)d_in[3];   // [d]
    float* out           = (float*)d_out;           // [b*t*d hidden][b*t entropy]

    int bt = in_sizes[1] / D;                       // b*t tokens
    long long blk_stride = (long long)in_sizes[0] / NBLK;  // b*t*d

    int grid = GRID < bt ? GRID : bt;
    reskip_kernel<<<grid, THREADS>>>(blocks, partial, wq, nw, out, bt, blk_stride);
}

// round 17
// speedup vs baseline: 1.3071x; 1.1405x over previous
#include <cuda_runtime.h>
#include <cuda_bf16.h>

#define D        1024
#define NBLK     6
#define NV       7            // 6 blocks + partial
#define THREADS  512
#define NWARP    16
#define REPS     1e-6f
#define INV_SCALE (1.0f/32.0f)   // 1/(sqrt(1024)*temperature)
#define GRID     296             // 2 CTAs/SM x 148 SMs, one exact wave

__global__ __launch_bounds__(THREADS, 2)
void reskip_kernel(const float* __restrict__ blocks,
                   const float* __restrict__ partial,
                   const float* __restrict__ w_query,
                   const float* __restrict__ norm_w,
                   float* __restrict__ out,
                   int bt, long long blk_stride)
{
    __shared__ float s_red[NWARP * 16];         // [warp][value]
    __shared__ float s_sc[NV];                  // per-vector scores
    __shared__ __align__(16) float s_coef[8];   // c[0..5]=w1*es[n], c[6]=pw, c[7]=0

    const int tid  = threadIdx.x;
    const int warp = tid >> 5, lane = tid & 31;
    const int j    = tid * 2;                   // this thread's 2 channels
    const int stride = gridDim.x;
    const long long dstep = (long long)stride * D;   // token-stride in floats

    // effective query = w_query * norm_weight (fp32)
    float2 q2  = *(const float2*)(w_query + j);
    float2 nw2 = *(const float2*)(norm_w  + j);
    const float q0 = q2.x * nw2.x, q1 = q2.y * nw2.y;

    int tok = blockIdx.x;
    if (tok >= bt) return;

    long long base = (long long)tok * D + j;

    // ---- prologue: load first token into cur registers
    float cx0[NV], cx1[NV];
    {
        #pragma unroll
        for (int n = 0; n < NBLK; n++) {
            float2 d = *(const float2*)(blocks + (long long)n * blk_stride + base);
            cx0[n] = d.x; cx1[n] = d.y;
        }
        float2 d = *(const float2*)(partial + base);
        cx0[6] = d.x; cx1[6] = d.y;
    }

    while (tok < bt) {
        const int ntok = tok + stride;

        // ---- score partials from cur data
        //   v[0..6] = q.x per vector, v[7..13] = x.x, v[14..15] = pad
        float v[16];
        #pragma unroll
        for (int n = 0; n < NV; n++) {
            v[n]     = fmaf(q1, cx1[n], q0 * cx0[n]);
            v[n + 7] = fmaf(cx1[n], cx1[n], cx0[n] * cx0[n]);
        }
        v[14] = 0.f; v[15] = 0.f;

        // ---- prefetch next token NOW; DRAM latency hides under the
        // butterfly/barrier/epilogue below. Tail-safe: re-load cur token.
        const long long nbase = base + ((ntok < bt) ? dstep : 0);
        float nx0[NV], nx1[NV];
        {
            #pragma unroll
            for (int n = 0; n < NBLK; n++) {
                float2 d = *(const float2*)(blocks + (long long)n * blk_stride + nbase);
                nx0[n] = d.x; nx1[n] = d.y;
            }
            float2 d = *(const float2*)(partial + nbase);
            nx0[6] = d.x; nx1[6] = d.y;
        }

        // ---- value-specializing butterfly: 16 values, 16 SHFL total.
        // Final: lane l holds the full-warp sum of value (l >> 1).
        #pragma unroll
        for (int off = 16, k = 8; off >= 2; off >>= 1, k >>= 1) {
            #pragma unroll
            for (int i = 0; i < 8; i++) {
                if (i < k) {
                    float send = (lane & off) ? v[i] : v[i + k];
                    float recv = __shfl_xor_sync(0xffffffffu, send, off);
                    v[i] = ((lane & off) ? v[i + k] : v[i]) + recv;
                }
            }
        }
        v[0] += __shfl_xor_sync(0xffffffffu, v[0], 1);

        if (!(lane & 1) && (lane >> 1) < 14)
            s_red[warp * 16 + (lane >> 1)] = v[0];
        __syncthreads();

        if (warp == 0) {
            float t = 0.f;
            if (lane < 14) {
                #pragma unroll
                for (int w = 0; w < NWARP; w++) t += s_red[w * 16 + lane];
            }
            float xxv = __shfl_sync(0xffffffffu, t, (lane + 7) & 31);
            if (lane < NV) {
                float inv = rsqrtf(xxv * (1.0f / (float)D) + REPS);
                s_sc[lane] = t * inv * INV_SCALE;
            }
            __syncwarp();

            if (lane == 0) {
                float sc[NV];
                #pragma unroll
                for (int n = 0; n < NV; n++) sc[n] = s_sc[n];

                // Phase-1 softmax, restructured: ONE fast division total.
                // ent1 = logl - (sum es_n * shifted_n) / lse
                float m1 = sc[0];
                #pragma unroll
                for (int n = 1; n < NBLK; n++) m1 = fmaxf(m1, sc[n]);
                float es[NBLK], lse = 0.f, dot = 0.f;
                #pragma unroll
                for (int n = 0; n < NBLK; n++) {
                    float sh = sc[n] - m1;
                    es[n] = __expf(sh);
                    lse  += es[n];
                    dot   = fmaf(es[n], sh, dot);
                }
                float logl = __logf(lse);
                float ent1 = logl - dot * __fdividef(1.f, lse);

                // Online-softmax merge with partial block (one more fast rcp)
                float ps    = sc[6];
                float mm    = fmaxf(m1, ps);
                float c1    = __expf(m1 - mm);
                float cp    = __expf(ps - mm);
                float denom = c1 * lse + cp;
                float invdn = __fdividef(1.f, denom);
                float w1w   = c1 * lse * invdn;     // phase1_weight
                float pw    = cp * invdn;           // partial_weight

                #pragma unroll
                for (int n = 0; n < NBLK; n++) s_coef[n] = w1w * es[n];
                s_coef[6] = pw;
                s_coef[7] = 0.f;

                float w1c = fmaxf(w1w, 1e-8f);
                float wpc = fmaxf(pw,  1e-8f);
                out[(long long)bt * D + tok] =
                    w1c * ent1 - w1c * __logf(w1c) - wpc * __logf(wpc);
            }
        }
        __syncthreads();

        // ---- epilogue: coefficients via 2 vector LDS, data from registers
        float4 cA = *(const float4*)&s_coef[0];
        float4 cB = *(const float4*)&s_coef[4];

        float o0, o1;
        o0 = cA.x * cx0[0];            o1 = cA.x * cx1[0];
        o0 = fmaf(cA.y, cx0[1], o0);   o1 = fmaf(cA.y, cx1[1], o1);
        o0 = fmaf(cA.z, cx0[2], o0);   o1 = fmaf(cA.z, cx1[2], o1);
        o0 = fmaf(cA.w, cx0[3], o0);   o1 = fmaf(cA.w, cx1[3], o1);
        o0 = fmaf(cB.x, cx0[4], o0);   o1 = fmaf(cB.x, cx1[4], o1);
        o0 = fmaf(cB.y, cx0[5], o0);   o1 = fmaf(cB.y, cx1[5], o1);
        o0 = fmaf(cB.z, cx0[6], o0);   o1 = fmaf(cB.z, cx1[6], o1);

        *(float2*)(out + base) = make_float2(o0, o1);

        // ---- rotate pipeline
        #pragma unroll
        for (int n = 0; n < NV; n++) { cx0[n] = nx0[n]; cx1[n] = nx1[n]; }
        base = nbase;
        tok  = ntok;
    }
}

extern "C" void kernel_launch(void* const* d_in, const int* in_sizes, int n_in,
                              void* d_out, int out_size)
{
    const float* blocks  = (const float*)d_in[0];   // [6, b, t, d]
    const float* partial = (const float*)d_in[1];   // [b, t, d]
    const float* wq      = (const float*)d_in[2];   // [d]
    const float* nw      = (const float*)d_in[3];   // [d]
    float* out           = (float*)d_out;           // [b*t*d hidden][b*t entropy]

    int bt = in_sizes[1] / D;                       // b*t tokens
    long long blk_stride = (long long)in_sizes[0] / NBLK;  // b*t*d

    int grid = GRID < bt ? GRID : bt;
    reskip_kernel<<<grid, THREADS>>>(blocks, partial, wq, nw, out, bt, blk_stride);
}